// round 4
// baseline (speedup 1.0000x reference)
#include <cuda_runtime.h>
#include <cuda_bf16.h>
#include <stdint.h>

#define HIDDEN   256
#define MAXN     100000
#define NPB      64            // nodes per block in the GEMM kernel
#define PF       8             // W2 prefetch distance (k iterations)
#define SMEM_A_F   (5 * HIDDEN)          // A0..A3, C
#define SMEM_C_F   (4 * NPB)             // centralities
#define SMEM_H_F   (HIDDEN * NPB)        // h tile [k][node]
#define SMEM_BYTES ((SMEM_A_F + SMEM_C_F + SMEM_H_F) * 4)

// Scratch (no cudaMalloc allowed)
__device__ int   g_deg[MAXN];
__device__ float g_A[5 * HIDDEN];   // A0,A1,A2,A3,C  (C includes b1)
__device__ int   g_is64;

// ---------------------------------------------------------------------------
// Kernel 0: dtype sniff. int64 node ids (<1e5) have zero hi-words; int32 data
// has random ids in those slots. Check 128 pairs.
// ---------------------------------------------------------------------------
__global__ void sniff_kernel(const unsigned int* __restrict__ p) {
    if (threadIdx.x == 0) {
        int is64 = 1;
        for (int i = 0; i < 128; ++i)
            if (p[2 * i + 1] != 0u) { is64 = 0; break; }
        g_is64 = is64;
    }
}

// ---------------------------------------------------------------------------
// Kernel 1: degree scatter  deg[col[e]] += 1   (4 edges per thread)
// ---------------------------------------------------------------------------
__global__ void scatter_deg_kernel(const void* __restrict__ edge, int E) {
    const bool is64 = (g_is64 != 0);
    int i = blockIdx.x * blockDim.x + threadIdx.x;
    int quarter = E >> 2;
    if (is64) {
        const long long* col = (const long long*)edge + (size_t)E;  // row 1
        if (i < quarter) {
            longlong2 v0 = reinterpret_cast<const longlong2*>(col)[2 * i];
            longlong2 v1 = reinterpret_cast<const longlong2*>(col)[2 * i + 1];
            atomicAdd(&g_deg[(int)v0.x], 1);
            atomicAdd(&g_deg[(int)v0.y], 1);
            atomicAdd(&g_deg[(int)v1.x], 1);
            atomicAdd(&g_deg[(int)v1.y], 1);
        }
        if (i == 0)
            for (int e = quarter << 2; e < E; ++e)
                atomicAdd(&g_deg[(int)col[e]], 1);
    } else {
        const int* col = (const int*)edge + (size_t)E;              // row 1
        if (i < quarter) {
            int4 v = reinterpret_cast<const int4*>(col)[i];
            atomicAdd(&g_deg[v.x], 1);
            atomicAdd(&g_deg[v.y], 1);
            atomicAdd(&g_deg[v.z], 1);
            atomicAdd(&g_deg[v.w], 1);
        }
        if (i == 0)
            for (int e = quarter << 2; e < E; ++e)
                atomicAdd(&g_deg[col[e]], 1);
    }
}

// ---------------------------------------------------------------------------
// Kernel 2: precompute A_g[k] = sum_j Wg[j] * W1[64g+j, k]
//           C[k] = sum_j bcat[j] * W1[j, k] + b1[k]
// ---------------------------------------------------------------------------
__global__ void precompute_kernel(
    const float* __restrict__ Wd, const float* __restrict__ bd,
    const float* __restrict__ Wb, const float* __restrict__ bb,
    const float* __restrict__ Wc, const float* __restrict__ bc,
    const float* __restrict__ We, const float* __restrict__ be,
    const float* __restrict__ W1, const float* __restrict__ b1)
{
    int k = threadIdx.x;
    float a0 = 0.f, a1 = 0.f, a2 = 0.f, a3 = 0.f, cc = 0.f;
#pragma unroll 8
    for (int j = 0; j < 64; ++j) {
        float w1a = W1[(j      ) * HIDDEN + k];
        float w1b = W1[(j +  64) * HIDDEN + k];
        float w1c = W1[(j + 128) * HIDDEN + k];
        float w1d = W1[(j + 192) * HIDDEN + k];
        a0 = fmaf(Wd[j], w1a, a0);  cc = fmaf(bd[j], w1a, cc);
        a1 = fmaf(Wb[j], w1b, a1);  cc = fmaf(bb[j], w1b, cc);
        a2 = fmaf(Wc[j], w1c, a2);  cc = fmaf(bc[j], w1c, cc);
        a3 = fmaf(We[j], w1d, a3);  cc = fmaf(be[j], w1d, cc);
    }
    cc += b1[k];
    g_A[0 * HIDDEN + k] = a0;
    g_A[1 * HIDDEN + k] = a1;
    g_A[2 * HIDDEN + k] = a2;
    g_A[3 * HIDDEN + k] = a3;
    g_A[4 * HIDDEN + k] = cc;
}

// ---------------------------------------------------------------------------
// Kernel 3: per-node  h = relu(c0*A0 + c1*A1 + c2*A2 + c3*A3 + C)
//           out[n,:] = h @ W2 + b2
// Phase A: warp = 32-wide k-chunk, lane = node (2 node-halves)
// Phase B: thread = output column; 64 nodes via 32 packed f32x2 accumulators;
//          W2 column double-buffered PF=8 ahead to cover L2 latency.
// ---------------------------------------------------------------------------
__global__ __launch_bounds__(256)
void fused_gemm_kernel(const float* __restrict__ noise,
                       const float* __restrict__ W2,
                       const float* __restrict__ b2,
                       float* __restrict__ out,
                       int N)
{
    extern __shared__ float smem[];
    float* A_sh = smem;                       // 5*256
    float* c_sh = A_sh + SMEM_A_F;            // 4*64  [g][node]
    float* h_sh = c_sh + SMEM_C_F;            // 256*64 [k][node]

    const int tid  = threadIdx.x;
    const int lane = tid & 31;
    const int warp = tid >> 5;
    const int base = blockIdx.x * NPB;

    // load A/C into shared
#pragma unroll
    for (int g = 0; g < 5; ++g) A_sh[g * HIDDEN + tid] = g_A[g * HIDDEN + tid];

    // centralities: warps 0,1 cover the 64 nodes
    if (warp < 2) {
        int nl = warp * 32 + lane;
        int n  = base + nl;
        float c0 = 0.f, c1 = 0.f, c2 = 0.f, c3 = 0.f;
        if (n < N) {
            float dc = (float)g_deg[n] * (1.0f / (float)(N - 1));
            float nz = noise[n];
            c0 = dc;
            c1 = fmaf(dc * nz, 0.1f, dc);
            c2 = 1.0f / (dc + 1e-8f);
            c3 = sqrtf(dc);
        }
        c_sh[0 * NPB + nl] = c0; c_sh[1 * NPB + nl] = c1;
        c_sh[2 * NPB + nl] = c2; c_sh[3 * NPB + nl] = c3;
    }
    __syncthreads();

    // Phase A: warp w owns k in [32w, 32w+32); lane = node, 2 halves
    {
        int k0 = warp * 32;
#pragma unroll
        for (int nh = 0; nh < 2; ++nh) {
            int nl = nh * 32 + lane;
            float c0 = c_sh[0 * NPB + nl], c1 = c_sh[1 * NPB + nl],
                  c2 = c_sh[2 * NPB + nl], c3 = c_sh[3 * NPB + nl];
#pragma unroll
            for (int i = 0; i < 32; ++i) {
                int k = k0 + i;
                float v = fmaf(c0, A_sh[k],
                          fmaf(c1, A_sh[HIDDEN + k],
                          fmaf(c2, A_sh[2 * HIDDEN + k],
                          fmaf(c3, A_sh[3 * HIDDEN + k], A_sh[4 * HIDDEN + k]))));
                h_sh[k * NPB + nl] = fmaxf(v, 0.0f);   // lane-stride 1
            }
        }
    }
    __syncthreads();

    // Phase B: out[n][tid] = sum_k h[k][n] * W2[k][tid]
    unsigned long long acc[NPB / 2];
#pragma unroll
    for (int j = 0; j < NPB / 2; ++j) acc[j] = 0ULL;

    const float* W2c = W2 + tid;
    uint32_t hbase = (uint32_t)__cvta_generic_to_shared(h_sh);

    // W2 column double-buffer: PF k-values ahead
    float wcur[PF];
#pragma unroll
    for (int j = 0; j < PF; ++j) wcur[j] = __ldg(&W2c[(size_t)j * HIDDEN]);

#pragma unroll 1
    for (int kb = 0; kb < HIDDEN; kb += PF) {
        float wnxt[PF];
        if (kb + PF < HIDDEN) {
#pragma unroll
            for (int j = 0; j < PF; ++j)
                wnxt[j] = __ldg(&W2c[(size_t)(kb + PF + j) * HIDDEN]);
        }
#pragma unroll
        for (int kk = 0; kk < PF; ++kk) {
            unsigned long long w2;
            asm("mov.b64 %0, {%1, %1};" : "=l"(w2) : "f"(wcur[kk]));
            uint32_t rowaddr = hbase + (uint32_t)(kb + kk) * (NPB * 4u);
            // j-loop in chunks of 2x ld.v2.b64 (4 accs) to bound live h regs
#pragma unroll
            for (int jc = 0; jc < NPB / 8; ++jc) {     // 8 chunks
                unsigned long long h0, h1, h2, h3;
                asm("ld.shared.v2.b64 {%0, %1}, [%2];"
                    : "=l"(h0), "=l"(h1) : "r"(rowaddr + jc * 32u));
                asm("ld.shared.v2.b64 {%0, %1}, [%2];"
                    : "=l"(h2), "=l"(h3) : "r"(rowaddr + jc * 32u + 16u));
                asm("fma.rn.f32x2 %0, %1, %2, %0;" : "+l"(acc[4 * jc    ]) : "l"(h0), "l"(w2));
                asm("fma.rn.f32x2 %0, %1, %2, %0;" : "+l"(acc[4 * jc + 1]) : "l"(h1), "l"(w2));
                asm("fma.rn.f32x2 %0, %1, %2, %0;" : "+l"(acc[4 * jc + 2]) : "l"(h2), "l"(w2));
                asm("fma.rn.f32x2 %0, %1, %2, %0;" : "+l"(acc[4 * jc + 3]) : "l"(h3), "l"(w2));
            }
        }
#pragma unroll
        for (int j = 0; j < PF; ++j) wcur[j] = wnxt[j];
    }

    float bbv = b2[tid];
#pragma unroll
    for (int j = 0; j < NPB / 2; ++j) {
        float x, y;
        asm("mov.b64 {%0, %1}, %2;" : "=f"(x), "=f"(y) : "l"(acc[j]));
        int n0 = base + 2 * j;
        int n1 = n0 + 1;
        if (n0 < N) out[(size_t)n0 * HIDDEN + tid] = x + bbv;
        if (n1 < N) out[(size_t)n1 * HIDDEN + tid] = y + bbv;
    }
}

// ---------------------------------------------------------------------------
// launch
// inputs: 0:x 1:edge_index 2:noise 3:W_deg 4:b_deg 5:W_bet 6:b_bet
//         7:W_clo 8:b_clo 9:W_eig 10:b_eig 11:W1 12:b1 13:W2 14:b2
// ---------------------------------------------------------------------------
extern "C" void kernel_launch(void* const* d_in, const int* in_sizes, int n_in,
                              void* d_out, int out_size)
{
    const int N = in_sizes[0] / HIDDEN;
    const int E = in_sizes[1] / 2;

    const void*  edge_index = d_in[1];
    const float* noise = (const float*)d_in[2];
    const float* Wd = (const float*)d_in[3],  *bd = (const float*)d_in[4];
    const float* Wb = (const float*)d_in[5],  *bb = (const float*)d_in[6];
    const float* Wc = (const float*)d_in[7],  *bc = (const float*)d_in[8];
    const float* We = (const float*)d_in[9],  *be = (const float*)d_in[10];
    const float* W1 = (const float*)d_in[11], *b1 = (const float*)d_in[12];
    const float* W2 = (const float*)d_in[13], *b2 = (const float*)d_in[14];
    float* out = (float*)d_out;

    // idempotent, capture-safe, no static state (harness rule)
    cudaFuncSetAttribute(fused_gemm_kernel,
                         cudaFuncAttributeMaxDynamicSharedMemorySize,
                         SMEM_BYTES);

    void* degp = nullptr;
    cudaGetSymbolAddress(&degp, g_deg);
    cudaMemsetAsync(degp, 0, (size_t)N * sizeof(int));

    sniff_kernel<<<1, 32>>>((const unsigned int*)edge_index);

    int quarter = (E >> 2);
    int nthreads = quarter > 0 ? quarter : 1;
    scatter_deg_kernel<<<(nthreads + 255) / 256, 256>>>(edge_index, E);

    precompute_kernel<<<1, 256>>>(Wd, bd, Wb, bb, Wc, bc, We, be, W1, b1);

    fused_gemm_kernel<<<(N + NPB - 1) / NPB, 256, SMEM_BYTES>>>(noise, W2, b2, out, N);
}

// round 9
// speedup vs baseline: 1.3481x; 1.3481x over previous
#include <cuda_runtime.h>
#include <cuda_bf16.h>
#include <stdint.h>

#define HIDDEN   256
#define MAXN     100000
#define NPB      64            // nodes per block in the GEMM kernel
#define SMEM_A_F   (5 * HIDDEN)          // A0..A3, C
#define SMEM_C_F   (4 * NPB)             // centralities
#define SMEM_H_F   (HIDDEN * NPB)        // h tile [k][node]
#define SMEM_BYTES ((SMEM_A_F + SMEM_C_F + SMEM_H_F) * 4)

// Scratch (no cudaMalloc allowed)
__device__ int   g_deg[MAXN];
__device__ float g_A[5 * HIDDEN];   // A0,A1,A2,A3,C  (C includes b1)

__device__ __forceinline__ unsigned long long pack2(float x, float y) {
    unsigned long long r;
    asm("mov.b64 %0, {%1, %2};" : "=l"(r) : "f"(x), "f"(y));
    return r;
}
__device__ __forceinline__ void ffma2(unsigned long long& a,
                                      unsigned long long b,
                                      unsigned long long c) {
    asm("fma.rn.f32x2 %0, %1, %2, %0;" : "+l"(a) : "l"(b), "l"(c));
}
__device__ __forceinline__ void unpack2(unsigned long long v, float& x, float& y) {
    asm("mov.b64 {%0, %1}, %2;" : "=f"(x), "=f"(y) : "l"(v));
}

// ---------------------------------------------------------------------------
// Kernel 1: degree scatter with per-block warp-parallel dtype sniff
// (int64 ids < 1e5 have zero hi-words in the first 128 packed pairs;
//  int32 has random ids there). 8 edges per thread.
// ---------------------------------------------------------------------------
__global__ void scatter_deg_kernel(const void* __restrict__ edge, int E) {
    __shared__ int s_is64;
    int tid = threadIdx.x;
    if (tid < 32) {
        const unsigned int* p = (const unsigned int*)edge;
        int bad = 0;
        for (int i = tid; i < 128; i += 32) bad |= (p[2 * i + 1] != 0u);
        unsigned m = __ballot_sync(0xffffffffu, bad);
        if (tid == 0) s_is64 = (m == 0u);
    }
    __syncthreads();
    const bool is64 = (s_is64 != 0);

    int i = blockIdx.x * blockDim.x + tid;
    int eighth = E >> 3;
    if (is64) {
        const long long* col = (const long long*)edge + (size_t)E;  // row 1
        if (i < eighth) {
#pragma unroll
            for (int q = 0; q < 4; ++q) {
                longlong2 v = reinterpret_cast<const longlong2*>(col)[4 * i + q];
                atomicAdd(&g_deg[(int)v.x], 1);
                atomicAdd(&g_deg[(int)v.y], 1);
            }
        }
        if (i == 0)
            for (int e = eighth << 3; e < E; ++e)
                atomicAdd(&g_deg[(int)col[e]], 1);
    } else {
        const int* col = (const int*)edge + (size_t)E;              // row 1
        if (i < eighth) {
#pragma unroll
            for (int q = 0; q < 2; ++q) {
                int4 v = reinterpret_cast<const int4*>(col)[2 * i + q];
                atomicAdd(&g_deg[v.x], 1);
                atomicAdd(&g_deg[v.y], 1);
                atomicAdd(&g_deg[v.z], 1);
                atomicAdd(&g_deg[v.w], 1);
            }
        }
        if (i == 0)
            for (int e = eighth << 3; e < E; ++e)
                atomicAdd(&g_deg[col[e]], 1);
    }
}

// ---------------------------------------------------------------------------
// Kernel 2: precompute A_g[k] = sum_j Wg[j] * W1[64g+j, k]
//           C[k] = sum_j bcat[j] * W1[j, k] + b1[k]
// ---------------------------------------------------------------------------
__global__ void precompute_kernel(
    const float* __restrict__ Wd, const float* __restrict__ bd,
    const float* __restrict__ Wb, const float* __restrict__ bb,
    const float* __restrict__ Wc, const float* __restrict__ bc,
    const float* __restrict__ We, const float* __restrict__ be,
    const float* __restrict__ W1, const float* __restrict__ b1)
{
    int k = threadIdx.x;
    float a0 = 0.f, a1 = 0.f, a2 = 0.f, a3 = 0.f, cc = 0.f;
#pragma unroll 8
    for (int j = 0; j < 64; ++j) {
        float w1a = W1[(j      ) * HIDDEN + k];
        float w1b = W1[(j +  64) * HIDDEN + k];
        float w1c = W1[(j + 128) * HIDDEN + k];
        float w1d = W1[(j + 192) * HIDDEN + k];
        a0 = fmaf(Wd[j], w1a, a0);  cc = fmaf(bd[j], w1a, cc);
        a1 = fmaf(Wb[j], w1b, a1);  cc = fmaf(bb[j], w1b, cc);
        a2 = fmaf(Wc[j], w1c, a2);  cc = fmaf(bc[j], w1c, cc);
        a3 = fmaf(We[j], w1d, a3);  cc = fmaf(be[j], w1d, cc);
    }
    cc += b1[k];
    g_A[0 * HIDDEN + k] = a0;
    g_A[1 * HIDDEN + k] = a1;
    g_A[2 * HIDDEN + k] = a2;
    g_A[3 * HIDDEN + k] = a3;
    g_A[4 * HIDDEN + k] = cc;
}

// ---------------------------------------------------------------------------
// Kernel 3: h = relu(c0*A0 + c1*A1 + c2*A2 + c3*A3 + C); out = h @ W2 + b2
// Phase A: warp = 32-wide k-chunk, lane = node (2 halves) -> h tile in smem
// Phase B: register tile 8 nodes x 8 cols per thread.
//   warp = node-group ty (h loads broadcast), lane = col-group tx.
//   Per k: 2 LDS.128 (h) + 2 LDG.128 (w, L1-hot) + 32 FFMA2  -> FMA-bound.
// ---------------------------------------------------------------------------
__global__ __launch_bounds__(256, 2)
void fused_gemm_kernel(const float* __restrict__ noise,
                       const float* __restrict__ W2,
                       const float* __restrict__ b2,
                       float* __restrict__ out,
                       int N)
{
    extern __shared__ float smem[];
    float* A_sh = smem;                       // 5*256
    float* c_sh = A_sh + SMEM_A_F;            // 4*64  [g][node]
    float* h_sh = c_sh + SMEM_C_F;            // 256*64 [k][node]

    const int tid  = threadIdx.x;
    const int lane = tid & 31;
    const int warp = tid >> 5;
    const int base = blockIdx.x * NPB;

    // load A/C into shared
#pragma unroll
    for (int g = 0; g < 5; ++g) A_sh[g * HIDDEN + tid] = g_A[g * HIDDEN + tid];

    // centralities: warps 0,1 cover the 64 nodes
    if (warp < 2) {
        int nl = warp * 32 + lane;
        int n  = base + nl;
        float c0 = 0.f, c1 = 0.f, c2 = 0.f, c3 = 0.f;
        if (n < N) {
            float inv = 1.0f / (float)(N - 1);
            float dc = (float)g_deg[n] * inv;
            float nz = __ldg(&noise[n]);
            c0 = dc;
            c1 = fmaf(dc * nz, 0.1f, dc);
            c2 = 1.0f / (dc + 1e-8f);
            c3 = sqrtf(dc);
        }
        c_sh[0 * NPB + nl] = c0; c_sh[1 * NPB + nl] = c1;
        c_sh[2 * NPB + nl] = c2; c_sh[3 * NPB + nl] = c3;
    }
    __syncthreads();

    // Phase A: warp w owns k in [32w, 32w+32); lane = node, 2 halves
    {
        int k0 = warp * 32;
#pragma unroll
        for (int nh = 0; nh < 2; ++nh) {
            int nl = nh * 32 + lane;
            float c0 = c_sh[0 * NPB + nl], c1 = c_sh[1 * NPB + nl],
                  c2 = c_sh[2 * NPB + nl], c3 = c_sh[3 * NPB + nl];
#pragma unroll
            for (int i = 0; i < 32; ++i) {
                int k = k0 + i;
                float v = fmaf(c0, A_sh[k],
                          fmaf(c1, A_sh[HIDDEN + k],
                          fmaf(c2, A_sh[2 * HIDDEN + k],
                          fmaf(c3, A_sh[3 * HIDDEN + k], A_sh[4 * HIDDEN + k]))));
                h_sh[k * NPB + nl] = fmaxf(v, 0.0f);   // lane-stride 1
            }
        }
    }
    __syncthreads();

    // Phase B: thread (ty=warp, tx=lane) owns nodes [ty*8, ty*8+8) and
    //          cols [tx*8, tx*8+8). acc[node][colpair]
    const int tx = lane;
    const int ty = warp;

    unsigned long long acc[8][4];
#pragma unroll
    for (int j = 0; j < 8; ++j)
#pragma unroll
        for (int c = 0; c < 4; ++c) acc[j][c] = 0ULL;

    const float4* wp0 = (const float4*)(W2 + tx * 8);      // 2 float4 per k row
    const float4* hp  = (const float4*)(h_sh + ty * 8);    // 2 float4 per k row

    // bias prefetch up-front: overlaps L2 latency with the first k iterations
    float4 bb0 = __ldg((const float4*)(b2 + tx * 8));
    float4 bb1 = __ldg((const float4*)(b2 + tx * 8) + 1);

    // prefetch k=0 weights
    float4 w0 = __ldg(&wp0[0]);
    float4 w1 = __ldg(&wp0[1]);

#pragma unroll 2
    for (int k = 0; k < HIDDEN; ++k) {
        // pack current weights FIRST (retires w0/w1 early, bounds live regs)
        unsigned long long wpk[4];
        wpk[0] = pack2(w0.x, w0.y); wpk[1] = pack2(w0.z, w0.w);
        wpk[2] = pack2(w1.x, w1.y); wpk[3] = pack2(w1.z, w1.w);

        // prefetch next k's weights (L1-hot after first warp)
        if (k + 1 < HIDDEN) {
            w0 = __ldg(&wp0[(k + 1) * (HIDDEN / 4)]);
            w1 = __ldg(&wp0[(k + 1) * (HIDDEN / 4) + 1]);
        }

        // h for this k: 8 floats, broadcast within warp
        float4 h0 = hp[k * (NPB / 4)];
        float4 h1 = hp[k * (NPB / 4) + 1];
        float hv[8] = {h0.x, h0.y, h0.z, h0.w, h1.x, h1.y, h1.z, h1.w};

#pragma unroll
        for (int j = 0; j < 8; ++j) {
            unsigned long long hd = pack2(hv[j], hv[j]);
            ffma2(acc[j][0], hd, wpk[0]);
            ffma2(acc[j][1], hd, wpk[1]);
            ffma2(acc[j][2], hd, wpk[2]);
            ffma2(acc[j][3], hd, wpk[3]);
        }
    }

    // epilogue: add b2, store 8 nodes x 8 cols (two STG.128 per node)
#pragma unroll
    for (int j = 0; j < 8; ++j) {
        int n = base + ty * 8 + j;
        if (n < N) {
            float x0, y0, x1, y1, x2, y2, x3, y3;
            unpack2(acc[j][0], x0, y0); unpack2(acc[j][1], x1, y1);
            unpack2(acc[j][2], x2, y2); unpack2(acc[j][3], x3, y3);
            float4 o0 = make_float4(x0 + bb0.x, y0 + bb0.y, x1 + bb0.z, y1 + bb0.w);
            float4 o1 = make_float4(x2 + bb1.x, y2 + bb1.y, x3 + bb1.z, y3 + bb1.w);
            float4* op = (float4*)(out + (size_t)n * HIDDEN + tx * 8);
            op[0] = o0;
            op[1] = o1;
        }
    }
}

// ---------------------------------------------------------------------------
// launch
// inputs: 0:x 1:edge_index 2:noise 3:W_deg 4:b_deg 5:W_bet 6:b_bet
//         7:W_clo 8:b_clo 9:W_eig 10:b_eig 11:W1 12:b1 13:W2 14:b2
// ---------------------------------------------------------------------------
extern "C" void kernel_launch(void* const* d_in, const int* in_sizes, int n_in,
                              void* d_out, int out_size)
{
    const int N = in_sizes[0] / HIDDEN;
    const int E = in_sizes[1] / 2;

    const void*  edge_index = d_in[1];
    const float* noise = (const float*)d_in[2];
    const float* Wd = (const float*)d_in[3],  *bd = (const float*)d_in[4];
    const float* Wb = (const float*)d_in[5],  *bb = (const float*)d_in[6];
    const float* Wc = (const float*)d_in[7],  *bc = (const float*)d_in[8];
    const float* We = (const float*)d_in[9],  *be = (const float*)d_in[10];
    const float* W1 = (const float*)d_in[11], *b1 = (const float*)d_in[12];
    const float* W2 = (const float*)d_in[13], *b2 = (const float*)d_in[14];
    float* out = (float*)d_out;

    // idempotent, capture-safe, no static state (harness rule)
    cudaFuncSetAttribute(fused_gemm_kernel,
                         cudaFuncAttributeMaxDynamicSharedMemorySize,
                         SMEM_BYTES);

    void* degp = nullptr;
    cudaGetSymbolAddress(&degp, g_deg);
    cudaMemsetAsync(degp, 0, (size_t)N * sizeof(int));

    // precompute first: its single block overlaps the scatter launch ramp
    precompute_kernel<<<1, 256>>>(Wd, bd, Wb, bb, Wc, bc, We, be, W1, b1);

    int eighth = (E >> 3);
    int nthreads = eighth > 0 ? eighth : 1;
    scatter_deg_kernel<<<(nthreads + 255) / 256, 256>>>(edge_index, E);

    fused_gemm_kernel<<<(N + NPB - 1) / NPB, 256, SMEM_BYTES>>>(noise, W2, b2, out, N);
}

// round 10
// speedup vs baseline: 1.5836x; 1.1748x over previous
#include <cuda_runtime.h>
#include <cuda_bf16.h>
#include <stdint.h>

#define HIDDEN   256
#define MAXN     100000
#define NPB      64            // nodes per block in the GEMM kernel
#define PBLK     16            // precompute blocks (16 W1 rows each)
#define SMEM_A_F   (5 * HIDDEN)          // A0..A3, C
#define SMEM_C_F   (4 * NPB)             // centralities
#define SMEM_H_F   (HIDDEN * NPB)        // h tile [k][node]
#define SMEM_BYTES ((SMEM_A_F + SMEM_C_F + SMEM_H_F) * 4)

// Scratch (no cudaMalloc allowed)
__device__ int   g_deg[MAXN];
__device__ float g_Apart[PBLK * HIDDEN];   // partial A_g sums (block-major)
__device__ float g_Cpart[PBLK * HIDDEN];   // partial C sums

__device__ __forceinline__ unsigned long long pack2(float x, float y) {
    unsigned long long r;
    asm("mov.b64 %0, {%1, %2};" : "=l"(r) : "f"(x), "f"(y));
    return r;
}
__device__ __forceinline__ void ffma2(unsigned long long& a,
                                      unsigned long long b,
                                      unsigned long long c) {
    asm("fma.rn.f32x2 %0, %1, %2, %0;" : "+l"(a) : "l"(b), "l"(c));
}
__device__ __forceinline__ void unpack2(unsigned long long v, float& x, float& y) {
    asm("mov.b64 {%0, %1}, %2;" : "=f"(x), "=f"(y) : "l"(v));
}

// ---------------------------------------------------------------------------
// Kernel 1: degree scatter with per-block warp-parallel dtype sniff
// (int64 ids < 1e5 have zero hi-words in the first 128 packed pairs;
//  int32 has random ids there). 8 edges per thread.
// ---------------------------------------------------------------------------
__global__ void scatter_deg_kernel(const void* __restrict__ edge, int E) {
    __shared__ int s_is64;
    int tid = threadIdx.x;
    if (tid < 32) {
        const unsigned int* p = (const unsigned int*)edge;
        int bad = 0;
        for (int i = tid; i < 128; i += 32) bad |= (p[2 * i + 1] != 0u);
        unsigned m = __ballot_sync(0xffffffffu, bad);
        if (tid == 0) s_is64 = (m == 0u);
    }
    __syncthreads();
    const bool is64 = (s_is64 != 0);

    int i = blockIdx.x * blockDim.x + tid;
    int eighth = E >> 3;
    if (is64) {
        const long long* col = (const long long*)edge + (size_t)E;  // row 1
        if (i < eighth) {
#pragma unroll
            for (int q = 0; q < 4; ++q) {
                longlong2 v = reinterpret_cast<const longlong2*>(col)[4 * i + q];
                atomicAdd(&g_deg[(int)v.x], 1);
                atomicAdd(&g_deg[(int)v.y], 1);
            }
        }
        if (i == 0)
            for (int e = eighth << 3; e < E; ++e)
                atomicAdd(&g_deg[(int)col[e]], 1);
    } else {
        const int* col = (const int*)edge + (size_t)E;              // row 1
        if (i < eighth) {
#pragma unroll
            for (int q = 0; q < 2; ++q) {
                int4 v = reinterpret_cast<const int4*>(col)[2 * i + q];
                atomicAdd(&g_deg[v.x], 1);
                atomicAdd(&g_deg[v.y], 1);
                atomicAdd(&g_deg[v.z], 1);
                atomicAdd(&g_deg[v.w], 1);
            }
        }
        if (i == 0)
            for (int e = eighth << 3; e < E; ++e)
                atomicAdd(&g_deg[col[e]], 1);
    }
}

// ---------------------------------------------------------------------------
// Kernel 2: precompute partials, 16 blocks x 256 threads.
// Block b owns W1 rows [16b, 16b+16) (all in group g = b/4).
//   g_Apart[b][k] = sum_t Wg[16*(b%4)+t]   * W1[(16b+t)*H + k]
//   g_Cpart[b][k] = sum_t bcat[16*(b%4)+t] * W1[(16b+t)*H + k]
// ---------------------------------------------------------------------------
__global__ void precompute_kernel(
    const float* __restrict__ Wd, const float* __restrict__ bd,
    const float* __restrict__ Wb, const float* __restrict__ bb,
    const float* __restrict__ Wc, const float* __restrict__ bc,
    const float* __restrict__ We, const float* __restrict__ be,
    const float* __restrict__ W1)
{
    const int b = blockIdx.x;
    const int k = threadIdx.x;
    const int g = b >> 2;
    const int j0 = (b & 3) * 16;            // offset within the 64-row group

    const float* Wg;
    const float* bg;
    if (g == 0)      { Wg = Wd; bg = bd; }
    else if (g == 1) { Wg = Wb; bg = bb; }
    else if (g == 2) { Wg = Wc; bg = bc; }
    else             { Wg = We; bg = be; }

    const float* W1r = W1 + (size_t)(b * 16) * HIDDEN + k;
    float pa = 0.f, pc = 0.f;
#pragma unroll
    for (int t = 0; t < 16; ++t) {
        float w1 = __ldg(&W1r[t * HIDDEN]);
        pa = fmaf(__ldg(&Wg[j0 + t]), w1, pa);
        pc = fmaf(__ldg(&bg[j0 + t]), w1, pc);
    }
    g_Apart[b * HIDDEN + k] = pa;
    g_Cpart[b * HIDDEN + k] = pc;
}

// ---------------------------------------------------------------------------
// Kernel 3: h = relu(c0*A0 + c1*A1 + c2*A2 + c3*A3 + C); out = h @ W2 + b2
// A/C assembled from precompute partials (L2-hot).
// Phase A: warp = 32-wide k-chunk, lane = node (2 halves) -> h tile in smem
// Phase B: register tile 8 nodes x 8 cols per thread. (unchanged from R9)
// ---------------------------------------------------------------------------
__global__ __launch_bounds__(256, 2)
void fused_gemm_kernel(const float* __restrict__ noise,
                       const float* __restrict__ W2,
                       const float* __restrict__ b2,
                       const float* __restrict__ b1,
                       float* __restrict__ out,
                       int N)
{
    extern __shared__ float smem[];
    float* A_sh = smem;                       // 5*256
    float* c_sh = A_sh + SMEM_A_F;            // 4*64  [g][node]
    float* h_sh = c_sh + SMEM_C_F;            // 256*64 [k][node]

    const int tid  = threadIdx.x;
    const int lane = tid & 31;
    const int warp = tid >> 5;
    const int base = blockIdx.x * NPB;

    // assemble A/C from partials (all L2-hot: 20 KB shared by 1563 blocks)
#pragma unroll
    for (int g = 0; g < 4; ++g) {
        float s = 0.f;
#pragma unroll
        for (int q = 0; q < 4; ++q)
            s += __ldg(&g_Apart[(g * 4 + q) * HIDDEN + tid]);
        A_sh[g * HIDDEN + tid] = s;
    }
    {
        float s = __ldg(&b1[tid]);
#pragma unroll
        for (int b = 0; b < PBLK; ++b)
            s += __ldg(&g_Cpart[b * HIDDEN + tid]);
        A_sh[4 * HIDDEN + tid] = s;
    }

    // centralities: warps 0,1 cover the 64 nodes
    if (warp < 2) {
        int nl = warp * 32 + lane;
        int n  = base + nl;
        float c0 = 0.f, c1 = 0.f, c2 = 0.f, c3 = 0.f;
        if (n < N) {
            float inv = 1.0f / (float)(N - 1);
            float dc = (float)g_deg[n] * inv;
            float nz = __ldg(&noise[n]);
            c0 = dc;
            c1 = fmaf(dc * nz, 0.1f, dc);
            c2 = 1.0f / (dc + 1e-8f);
            c3 = sqrtf(dc);
        }
        c_sh[0 * NPB + nl] = c0; c_sh[1 * NPB + nl] = c1;
        c_sh[2 * NPB + nl] = c2; c_sh[3 * NPB + nl] = c3;
    }
    __syncthreads();

    // Phase A: warp w owns k in [32w, 32w+32); lane = node, 2 halves
    {
        int k0 = warp * 32;
#pragma unroll
        for (int nh = 0; nh < 2; ++nh) {
            int nl = nh * 32 + lane;
            float c0 = c_sh[0 * NPB + nl], c1 = c_sh[1 * NPB + nl],
                  c2 = c_sh[2 * NPB + nl], c3 = c_sh[3 * NPB + nl];
#pragma unroll
            for (int i = 0; i < 32; ++i) {
                int k = k0 + i;
                float v = fmaf(c0, A_sh[k],
                          fmaf(c1, A_sh[HIDDEN + k],
                          fmaf(c2, A_sh[2 * HIDDEN + k],
                          fmaf(c3, A_sh[3 * HIDDEN + k], A_sh[4 * HIDDEN + k]))));
                h_sh[k * NPB + nl] = fmaxf(v, 0.0f);   // lane-stride 1
            }
        }
    }
    __syncthreads();

    // Phase B: thread (ty=warp, tx=lane) owns nodes [ty*8, ty*8+8) and
    //          cols [tx*8, tx*8+8). acc[node][colpair]
    const int tx = lane;
    const int ty = warp;

    unsigned long long acc[8][4];
#pragma unroll
    for (int j = 0; j < 8; ++j)
#pragma unroll
        for (int c = 0; c < 4; ++c) acc[j][c] = 0ULL;

    const float4* wp0 = (const float4*)(W2 + tx * 8);      // 2 float4 per k row
    const float4* hp  = (const float4*)(h_sh + ty * 8);    // 2 float4 per k row

    // bias prefetch up-front: overlaps L2 latency with the first k iterations
    float4 bb0 = __ldg((const float4*)(b2 + tx * 8));
    float4 bb1 = __ldg((const float4*)(b2 + tx * 8) + 1);

    // prefetch k=0 weights
    float4 w0 = __ldg(&wp0[0]);
    float4 w1 = __ldg(&wp0[1]);

#pragma unroll 2
    for (int k = 0; k < HIDDEN; ++k) {
        // pack current weights FIRST (retires w0/w1 early, bounds live regs)
        unsigned long long wpk[4];
        wpk[0] = pack2(w0.x, w0.y); wpk[1] = pack2(w0.z, w0.w);
        wpk[2] = pack2(w1.x, w1.y); wpk[3] = pack2(w1.z, w1.w);

        // prefetch next k's weights (L1-hot after first warp)
        if (k + 1 < HIDDEN) {
            w0 = __ldg(&wp0[(k + 1) * (HIDDEN / 4)]);
            w1 = __ldg(&wp0[(k + 1) * (HIDDEN / 4) + 1]);
        }

        // h for this k: 8 floats, broadcast within warp
        float4 h0 = hp[k * (NPB / 4)];
        float4 h1 = hp[k * (NPB / 4) + 1];
        float hv[8] = {h0.x, h0.y, h0.z, h0.w, h1.x, h1.y, h1.z, h1.w};

#pragma unroll
        for (int j = 0; j < 8; ++j) {
            unsigned long long hd = pack2(hv[j], hv[j]);
            ffma2(acc[j][0], hd, wpk[0]);
            ffma2(acc[j][1], hd, wpk[1]);
            ffma2(acc[j][2], hd, wpk[2]);
            ffma2(acc[j][3], hd, wpk[3]);
        }
    }

    // epilogue: add b2, store 8 nodes x 8 cols (two STG.128 per node)
#pragma unroll
    for (int j = 0; j < 8; ++j) {
        int n = base + ty * 8 + j;
        if (n < N) {
            float x0, y0, x1, y1, x2, y2, x3, y3;
            unpack2(acc[j][0], x0, y0); unpack2(acc[j][1], x1, y1);
            unpack2(acc[j][2], x2, y2); unpack2(acc[j][3], x3, y3);
            float4 o0 = make_float4(x0 + bb0.x, y0 + bb0.y, x1 + bb0.z, y1 + bb0.w);
            float4 o1 = make_float4(x2 + bb1.x, y2 + bb1.y, x3 + bb1.z, y3 + bb1.w);
            float4* op = (float4*)(out + (size_t)n * HIDDEN + tx * 8);
            op[0] = o0;
            op[1] = o1;
        }
    }
}

// ---------------------------------------------------------------------------
// launch
// inputs: 0:x 1:edge_index 2:noise 3:W_deg 4:b_deg 5:W_bet 6:b_bet
//         7:W_clo 8:b_clo 9:W_eig 10:b_eig 11:W1 12:b1 13:W2 14:b2
// ---------------------------------------------------------------------------
extern "C" void kernel_launch(void* const* d_in, const int* in_sizes, int n_in,
                              void* d_out, int out_size)
{
    const int N = in_sizes[0] / HIDDEN;
    const int E = in_sizes[1] / 2;

    const void*  edge_index = d_in[1];
    const float* noise = (const float*)d_in[2];
    const float* Wd = (const float*)d_in[3],  *bd = (const float*)d_in[4];
    const float* Wb = (const float*)d_in[5],  *bb = (const float*)d_in[6];
    const float* Wc = (const float*)d_in[7],  *bc = (const float*)d_in[8];
    const float* We = (const float*)d_in[9],  *be = (const float*)d_in[10];
    const float* W1 = (const float*)d_in[11], *b1 = (const float*)d_in[12];
    const float* W2 = (const float*)d_in[13], *b2 = (const float*)d_in[14];
    float* out = (float*)d_out;

    // idempotent, capture-safe, no static state (harness rule)
    cudaFuncSetAttribute(fused_gemm_kernel,
                         cudaFuncAttributeMaxDynamicSharedMemorySize,
                         SMEM_BYTES);

    void* degp = nullptr;
    cudaGetSymbolAddress(&degp, g_deg);
    cudaMemsetAsync(degp, 0, (size_t)N * sizeof(int));

    // precompute (16 blocks) overlaps the scatter launch ramp
    precompute_kernel<<<PBLK, 256>>>(Wd, bd, Wb, bb, Wc, bc, We, be, W1);

    int eighth = (E >> 3);
    int nthreads = eighth > 0 ? eighth : 1;
    scatter_deg_kernel<<<(nthreads + 255) / 256, 256>>>(edge_index, E);

    fused_gemm_kernel<<<(N + NPB - 1) / NPB, 256, SMEM_BYTES>>>(noise, W2, b2, b1, out, N);
}